// round 15
// baseline (speedup 1.0000x reference)
#include <cuda_runtime.h>
#include <cstdint>
#include <math.h>

#define DMODEL 1024
#define DFF    4096
#define NHEADS 16
#define DKV    64
#define BATCH  8
#define SEQ    1024
#define MROWS  (BATCH*SEQ)    // 8192
#define BH     (BATCH*NHEADS) // 128

// ---------------- scratch (no allocations allowed) ----------------
__device__ __align__(256) float g_q[BH*SEQ*DKV];        // [B,H,S,Dk] rounded
__device__ __align__(256) float g_k[BH*SEQ*DKV];        // [B,H,S,Dk] rounded
__device__ __align__(256) float g_vT[BH*DKV*SEQ];       // [B,H,Dv,S] rounded
__device__ __align__(256) float g_ctx[MROWS*DMODEL];    // rounded
__device__ __align__(256) float g_tmp[MROWS*DMODEL];    // pre-LN fp32
__device__ __align__(256) float g_ao[MROWS*DMODEL];     // LN1 fp32 (residual)
__device__ __align__(256) float g_aor[MROWS*DMODEL];    // LN1 rounded
__device__ __align__(256) float g_xr[MROWS*DMODEL];     // x rounded
__device__ __align__(256) float g_h[(size_t)MROWS*DFF]; // hidden rounded
__device__ __align__(256) float g_wqT[DMODEL*DMODEL];   // W^T rounded (K-major)
__device__ __align__(256) float g_wkT[DMODEL*DMODEL];
__device__ __align__(256) float g_wvT[DMODEL*DMODEL];
__device__ __align__(256) float g_woT[DMODEL*DMODEL];
__device__ __align__(256) float g_w1T[(size_t)DMODEL*DFF];
__device__ __align__(256) float g_w2T[(size_t)DFF*DMODEL];

// ---------------- helpers ----------------
__device__ __forceinline__ unsigned f2tf(float x) {
    unsigned u;
    asm("cvt.rna.tf32.f32 %0, %1;" : "=r"(u) : "f"(x));
    return u;
}
__device__ __forceinline__ float f2tff(float x) { return __uint_as_float(f2tf(x)); }

__device__ __forceinline__ unsigned sptr(const void* p) {
    return (unsigned)__cvta_generic_to_shared(p);
}
#define CP_ASYNC16(dst, src) \
    asm volatile("cp.async.cg.shared.global [%0], [%1], 16;" :: "r"(dst), "l"(src))
#define CP_COMMIT() asm volatile("cp.async.commit_group;")
#define CP_WAIT(n)  asm volatile("cp.async.wait_group %0;" :: "n"(n))

#define LDSM4(r0, r1, r2, r3, a) \
    asm volatile("ldmatrix.sync.aligned.m8n8.x4.shared.b16 {%0,%1,%2,%3}, [%4];" \
                 : "=r"(r0), "=r"(r1), "=r"(r2), "=r"(r3) : "r"(a))

__device__ __forceinline__ void mma_tf32(float* c, const unsigned* a, const unsigned* b) {
    asm volatile(
        "mma.sync.aligned.m16n8k8.row.col.f32.tf32.tf32.f32 "
        "{%0,%1,%2,%3},{%4,%5,%6,%7},{%8,%9},{%0,%1,%2,%3};"
        : "+f"(c[0]), "+f"(c[1]), "+f"(c[2]), "+f"(c[3])
        : "r"(a[0]), "r"(a[1]), "r"(a[2]), "r"(a[3]), "r"(b[0]), "r"(b[1]));
}

// ---------------- prep kernels ----------------
__global__ void round_tf(const float* __restrict__ in, float* __restrict__ out, int n4)
{
    int i = blockIdx.x * blockDim.x + threadIdx.x;
    if (i < n4) {
        float4 v = ((const float4*)in)[i];
        v.x = f2tff(v.x); v.y = f2tff(v.y); v.z = f2tff(v.z); v.w = f2tff(v.w);
        ((float4*)out)[i] = v;
    }
}

// in [R][C] -> out [C][R], tf32-rounded
__global__ void transpose_round(const float* __restrict__ in, float* __restrict__ out,
                                int R, int C)
{
    __shared__ float t[32][33];
    const int c0 = blockIdx.x * 32, r0 = blockIdx.y * 32;
    const int tx = threadIdx.x, ty = threadIdx.y;   // 32 x 8
    #pragma unroll
    for (int i = 0; i < 32; i += 8)
        t[ty + i][tx] = in[(size_t)(r0 + ty + i) * C + c0 + tx];
    __syncthreads();
    #pragma unroll
    for (int i = 0; i < 32; i += 8)
        out[(size_t)(c0 + ty + i) * R + r0 + tx] = f2tff(t[tx][ty + i]);
}

// =====================================================================
// mma.sync tf32 GEMM, ldmatrix fragments, cp.async staging, BK=32.
// D[m][n] = sum_k A[m][k] * B[n][k], both operands K-major, pre-rounded.
// Block tile 128 x NTILE, 8 warps (2M x 4N), warp tile 64 x (NTILE/4).
// MODE: 1 q/k-remap(+bias,round; blockIdx.z selects {B,bias,C} vs {B2,bias2,C2})
//       2 +bias+resid  3 relu(+bias,round)
//       6 vT transposed remap(+bias-by-row,round)
// =====================================================================
template<int NTILE, int MODE>
__global__ void __launch_bounds__(256, 2) tc_mma(
    const float* __restrict__ A, const float* __restrict__ B,
    const float* __restrict__ bias, const float* __restrict__ resid,
    float* __restrict__ C,
    const float* __restrict__ B2, const float* __restrict__ bias2,
    float* __restrict__ C2,
    int K, int N)
{
    constexpr int S = 3;
    constexpr int ABYTES = 128 * 128;          // 128 rows x 128B
    constexpr int BBYTES = NTILE * 128;
    constexpr int STAGE  = ABYTES + BBYTES;
    constexpr int NP = NTILE / 64;             // ldmatrix x4 B pairs per warp
    constexpr int NT = NTILE / 32;             // 8-wide n atoms per warp

    extern __shared__ __align__(128) char smem[];
    const uint32_t ST0 = sptr(smem);

    const int tid = threadIdx.x;
    const int lane = tid & 31, wid = tid >> 5;
    const int warpM = wid >> 2, warpN = wid & 3;
    const int g = lane >> 2, t = lane & 3;
    const int sub = lane >> 3, lr = lane & 7;
    const int asel = sub >> 1, bsel = sub & 1;

    const int bm = blockIdx.y, bn = blockIdx.x;
    if (MODE == 1 && blockIdx.z == 1) { B = B2; bias = bias2; C = C2; }

    const float* Aload = A + (size_t)bm * 128 * K;
    const float* Bload = B + (size_t)bn * NTILE * K;

    const int arow = tid >> 1, ahalf = tid & 1;
    const float* Ag = Aload + (size_t)arow * K + ahalf * 16;
    const int brow = (NTILE == 128) ? (tid >> 1) : (tid >> 2);
    const int bu0  = (NTILE == 128) ? (ahalf * 4) : ((tid & 3) * 2);
    const float* Bg = Bload + (size_t)brow * K + bu0 * 4;

    auto load_chunk = [&](int ch) {
        const uint32_t stA = ST0 + (ch % S) * STAGE;
        const uint32_t stB = stA + ABYTES;
        const float* ap = Ag + ch * 32;
        const uint32_t abase = stA + arow * 128;
        #pragma unroll
        for (int i = 0; i < 4; i++) {
            const int u = ahalf * 4 + i;
            CP_ASYNC16(abase + ((u ^ (arow & 7)) << 4), ap + i * 4);
        }
        const float* bp = Bg + ch * 32;
        const uint32_t bbase = stB + brow * 128;
        #pragma unroll
        for (int i = 0; i < (NTILE == 128 ? 4 : 2); i++) {
            const int u = bu0 + i;
            CP_ASYNC16(bbase + ((u ^ (brow & 7)) << 4), bp + i * 4);
        }
    };

    uint32_t arow_b[4], brow_b[NP];
    #pragma unroll
    for (int mt = 0; mt < 4; mt++)
        arow_b[mt] = (warpM * 64 + mt * 16 + (sub & 1) * 8 + lr) * 128;
    #pragma unroll
    for (int np = 0; np < NP; np++)
        brow_b[np] = (warpN * (NTILE / 4) + np * 16 + asel * 8 + lr) * 128;

    float acc[4][NT][4];
    #pragma unroll
    for (int i = 0; i < 4; i++)
        #pragma unroll
        for (int j = 0; j < NT; j++)
            #pragma unroll
            for (int r = 0; r < 4; r++) acc[i][j][r] = 0.f;

    const int nch = K >> 5;

    #pragma unroll
    for (int c = 0; c < S - 1; c++) {
        if (c < nch) load_chunk(c);
        CP_COMMIT();
    }

    for (int ch = 0; ch < nch; ch++) {
        CP_WAIT(S - 2);
        __syncthreads();
        if (ch + S - 1 < nch) load_chunk(ch + S - 1);
        CP_COMMIT();

        const uint32_t Ast = ST0 + (ch % S) * STAGE;
        const uint32_t Bst = Ast + ABYTES;
        #pragma unroll
        for (int ks = 0; ks < 4; ks++) {
            const uint32_t aoff = (uint32_t)((((ks << 1) + asel) ^ lr) << 4);
            const uint32_t boff = (uint32_t)((((ks << 1) + bsel) ^ lr) << 4);
            unsigned af[4][4];
            #pragma unroll
            for (int mt = 0; mt < 4; mt++)
                LDSM4(af[mt][0], af[mt][1], af[mt][2], af[mt][3],
                      Ast + arow_b[mt] + aoff);
            unsigned bf[NP][4];
            #pragma unroll
            for (int np = 0; np < NP; np++)
                LDSM4(bf[np][0], bf[np][1], bf[np][2], bf[np][3],
                      Bst + brow_b[np] + boff);
            #pragma unroll
            for (int mt = 0; mt < 4; mt++)
                #pragma unroll
                for (int np = 0; np < NP; np++) {
                    mma_tf32(acc[mt][np * 2],     af[mt], &bf[np][0]);
                    mma_tf32(acc[mt][np * 2 + 1], af[mt], &bf[np][2]);
                }
        }
    }

    // ---- epilogue ----
    #pragma unroll
    for (int mt = 0; mt < 4; mt++) {
        const int r0 = bm * 128 + warpM * 64 + mt * 16 + g;
        const int r1 = r0 + 8;
        #pragma unroll
        for (int nt = 0; nt < NT; nt++) {
            const int c = bn * NTILE + warpN * (NTILE / 4) + nt * 8 + 2 * t;
            float2 lo = make_float2(acc[mt][nt][0], acc[mt][nt][1]);  // row r0
            float2 hi = make_float2(acc[mt][nt][2], acc[mt][nt][3]);  // row r1

            if (MODE == 1 || MODE == 2 || MODE == 3) {
                const float2 bv = *(const float2*)(bias + c);
                lo.x += bv.x; lo.y += bv.y; hi.x += bv.x; hi.y += bv.y;
            }
            if (MODE == 6) {
                const float b0 = bias[r0], b1 = bias[r1];
                lo.x = f2tff(lo.x + b0); lo.y = f2tff(lo.y + b0);
                hi.x = f2tff(hi.x + b1); hi.y = f2tff(hi.y + b1);
            }
            if (MODE == 2) {
                const float2 q0 = *(const float2*)(resid + (size_t)r0 * N + c);
                const float2 q1 = *(const float2*)(resid + (size_t)r1 * N + c);
                lo.x += q0.x; lo.y += q0.y; hi.x += q1.x; hi.y += q1.y;
            }
            if (MODE == 3) {
                lo.x = f2tff(fmaxf(lo.x, 0.f)); lo.y = f2tff(fmaxf(lo.y, 0.f));
                hi.x = f2tff(fmaxf(hi.x, 0.f)); hi.y = f2tff(fmaxf(hi.y, 0.f));
            }

            if (MODE == 1) {
                lo.x = f2tff(lo.x); lo.y = f2tff(lo.y);
                hi.x = f2tff(hi.x); hi.y = f2tff(hi.y);
                const int h = c >> 6, d = c & 63;
                const int bb0 = r0 >> 10, s0 = r0 & 1023;
                const int bb1 = r1 >> 10, s1 = r1 & 1023;
                *(float2*)(C + (((size_t)(bb0*NHEADS + h))*SEQ + s0)*DKV + d) = lo;
                *(float2*)(C + (((size_t)(bb1*NHEADS + h))*SEQ + s1)*DKV + d) = hi;
            } else if (MODE == 6) {
                const int b = c >> 10, s = c & 1023;
                const int h0 = r0 >> 6, d0 = r0 & 63;
                const int h1 = r1 >> 6, d1 = r1 & 63;
                *(float2*)(C + (((size_t)(b*NHEADS + h0))*DKV + d0)*SEQ + s) = lo;
                *(float2*)(C + (((size_t)(b*NHEADS + h1))*DKV + d1)*SEQ + s) = hi;
            } else {
                *(float2*)(C + (size_t)r0 * N + c) = lo;
                *(float2*)(C + (size_t)r1 * N + c) = hi;
            }
        }
    }
}

// =====================================================================
// Fully fused attention: scores + mask + softmax + (attn write) + ctx.
// Block: 32 q-rows x all 1024 keys, 512 thr = 16 warps (2M x 8N).
// Phase 1: scores into acc[8][2][4] (keys chunked by 128, double-buffered).
// Stats:   row max/sum via shuffle + smem.
// Phase 2: per chunk: normalized+rounded P -> gmem attn AND smem A-tile;
//          V chunk (from vT, K-major over s) double-buffered; 16x m16n8k8
//          mma accumulates ctx[32x64] (warp = 16 rows x 8 dv cols).
// =====================================================================
__global__ void __launch_bounds__(512, 1) fused_attn(
    const float* __restrict__ q, const float* __restrict__ k,
    const float* __restrict__ vT, const unsigned char* __restrict__ mask,
    float* __restrict__ attn, float* __restrict__ ctx)
{
    extern __shared__ __align__(128) char smem[];
    const uint32_t SA = sptr(smem);            // phase1 Q: 2kc x 32r x 128B = 8KB
    const uint32_t SB = SA + 8192;             // phase1 K: 2 stages x 32KB
    const uint32_t PS = SA;                    // phase2 P: 16KB (over SA+SB head)
    const uint32_t VS = SA + 16384;            // phase2 V: 2 stages x 32KB
    float* stats = (float*)(smem + 81920);     // [32][9]

    const int tid = threadIdx.x;
    const int lane = tid & 31, wid = tid >> 5;
    const int wM = wid >> 3, wN = wid & 7;
    const int g = lane >> 2, t = lane & 3;
    const int sub = lane >> 3, lr = lane & 7;
    const int asel = sub >> 1, bsel = sub & 1;

    const int bz = blockIdx.y;
    const int row0 = blockIdx.x * 32;
    const float* qg = q + (size_t)bz * SEQ * DKV + (size_t)row0 * DKV;
    const float* kg = k + (size_t)bz * SEQ * DKV;
    const float* vg = vT + (size_t)bz * DKV * SEQ;
    float* ag = attn + (size_t)bz * SEQ * SEQ;
    const unsigned char* mb = mask + (size_t)(bz >> 4) * SEQ * SEQ;

    // load Q tile (8KB): thread -> one 16B unit
    {
        const int u = tid & 7, row = (tid >> 3) & 31, kc = tid >> 8;
        CP_ASYNC16(SA + kc * 4096 + row * 128 + ((u ^ (row & 7)) << 4),
                   qg + (size_t)row * DKV + kc * 32 + u * 4);
    }
    auto loadK = [&](int c, int st) {
        const uint32_t stB = SB + st * 32768;
        const float* kb = kg + (size_t)c * 128 * DKV;
        #pragma unroll
        for (int i = 0; i < 4; i++) {
            const int idx = tid + i * 512;
            const int u = idx & 7, krow = (idx >> 3) & 127, kc = idx >> 10;
            CP_ASYNC16(stB + kc * 16384 + krow * 128 + ((u ^ (krow & 7)) << 4),
                       kb + (size_t)krow * DKV + kc * 32 + u * 4);
        }
    };
    auto loadV = [&](int c, int st) {
        const float* vb = vg + (size_t)c * 128;
        #pragma unroll
        for (int i = 0; i < 4; i++) {
            const int idx = tid + i * 512;
            const int u = idx & 7, row = (idx >> 3) & 63, kc = idx >> 9;
            CP_ASYNC16(VS + st * 32768 + kc * 8192 + row * 128 + ((u ^ (row & 7)) << 4),
                       vb + (size_t)row * SEQ + kc * 32 + u * 4);
        }
    };

    float acc[8][2][4];
    #pragma unroll
    for (int c = 0; c < 8; c++)
        #pragma unroll
        for (int a = 0; a < 2; a++)
            #pragma unroll
            for (int r = 0; r < 4; r++) acc[c][a][r] = 0.f;

    loadK(0, 0); CP_COMMIT();

    const uint32_t arow128 = (wM * 16 + (sub & 1) * 8 + lr) * 128;
    const uint32_t brow128 = (wN * 16 + asel * 8 + lr) * 128;

    for (int c = 0; c < 8; c++) {
        if (c < 7) { loadK(c + 1, (c + 1) & 1); CP_COMMIT(); CP_WAIT(1); }
        else       { CP_WAIT(0); }
        __syncthreads();
        const uint32_t stB = SB + (c & 1) * 32768;
        #pragma unroll
        for (int ks = 0; ks < 8; ks++) {
            const int kc = ks >> 2;
            const uint32_t aoff = (uint32_t)(((((ks & 3) << 1) + asel) ^ lr) << 4);
            const uint32_t boff = (uint32_t)(((((ks & 3) << 1) + bsel) ^ lr) << 4);
            unsigned af[4], bf[4];
            LDSM4(af[0], af[1], af[2], af[3], SA + kc * 4096 + arow128 + aoff);
            LDSM4(bf[0], bf[1], bf[2], bf[3], stB + kc * 16384 + brow128 + boff);
            mma_tf32(acc[c][0], af, &bf[0]);
            mma_tf32(acc[c][1], af, &bf[2]);
        }
        __syncthreads();
    }

    // ---- prefetch V chunk 0 while doing stats ----
    loadV(0, 0); CP_COMMIT();

    // ---- softmax stats ----
    const int lr0 = wM * 16 + g;          // local rows
    const int lr1 = lr0 + 8;
    const size_t gr0 = (size_t)(row0 + lr0) * SEQ;
    const size_t gr1 = (size_t)(row0 + lr1) * SEQ;

    float m0 = -1e30f, m1 = -1e30f;
    #pragma unroll
    for (int c = 0; c < 8; c++)
        #pragma unroll
        for (int a = 0; a < 2; a++) {
            const int key = c * 128 + wN * 16 + a * 8 + 2 * t;
            float v0 = acc[c][a][0] * 0.125f, v1 = acc[c][a][1] * 0.125f;
            float v2 = acc[c][a][2] * 0.125f, v3 = acc[c][a][3] * 0.125f;
            if (mb[gr0 + key])     v0 = -1e9f;
            if (mb[gr0 + key + 1]) v1 = -1e9f;
            if (mb[gr1 + key])     v2 = -1e9f;
            if (mb[gr1 + key + 1]) v3 = -1e9f;
            acc[c][a][0] = v0; acc[c][a][1] = v1;
            acc[c][a][2] = v2; acc[c][a][3] = v3;
            m0 = fmaxf(m0, fmaxf(v0, v1));
            m1 = fmaxf(m1, fmaxf(v2, v3));
        }
    m0 = fmaxf(m0, __shfl_xor_sync(~0u, m0, 1));
    m0 = fmaxf(m0, __shfl_xor_sync(~0u, m0, 2));
    m1 = fmaxf(m1, __shfl_xor_sync(~0u, m1, 1));
    m1 = fmaxf(m1, __shfl_xor_sync(~0u, m1, 2));
    if (t == 0) { stats[lr0 * 9 + wN] = m0; stats[lr1 * 9 + wN] = m1; }
    __syncthreads();
    float M0 = stats[lr0 * 9], M1 = stats[lr1 * 9];
    #pragma unroll
    for (int i = 1; i < 8; i++) {
        M0 = fmaxf(M0, stats[lr0 * 9 + i]);
        M1 = fmaxf(M1, stats[lr1 * 9 + i]);
    }
    __syncthreads();

    float s0 = 0.f, s1 = 0.f;
    #pragma unroll
    for (int c = 0; c < 8; c++)
        #pragma unroll
        for (int a = 0; a < 2; a++) {
            float e0 = __expf(acc[c][a][0] - M0), e1 = __expf(acc[c][a][1] - M0);
            float e2 = __expf(acc[c][a][2] - M1), e3 = __expf(acc[c][a][3] - M1);
            acc[c][a][0] = e0; acc[c][a][1] = e1;
            acc[c][a][2] = e2; acc[c][a][3] = e3;
            s0 += e0 + e1; s1 += e2 + e3;
        }
    s0 += __shfl_xor_sync(~0u, s0, 1); s0 += __shfl_xor_sync(~0u, s0, 2);
    s1 += __shfl_xor_sync(~0u, s1, 1); s1 += __shfl_xor_sync(~0u, s1, 2);
    if (t == 0) { stats[lr0 * 9 + wN] = s0; stats[lr1 * 9 + wN] = s1; }
    __syncthreads();
    float S0 = 0.f, S1 = 0.f;
    #pragma unroll
    for (int i = 0; i < 8; i++) { S0 += stats[lr0 * 9 + i]; S1 += stats[lr1 * 9 + i]; }
    const float inv0 = 1.f / S0, inv1 = 1.f / S1;

    // ---- phase 2: write attn + P-smem, then ctx mma per chunk ----
    const int pkc = wN >> 1;                  // P kc group of this thread's keys
    const int pub = (wN & 1) * 4;             // base unit within kc
    float acc2[4] = {0.f, 0.f, 0.f, 0.f};
    const uint32_t parow = wM * 16 + (sub & 1) * 8 + lr;   // phase2 A rows
    const uint32_t pbrow = wN * 8 + lr;                    // phase2 B rows (dv)

    for (int c = 0; c < 8; c++) {
        // normalize + round; write gmem attn + swizzled P tile
        #pragma unroll
        for (int a = 0; a < 2; a++) {
            const int key = c * 128 + wN * 16 + a * 8 + 2 * t;
            float2 w0 = make_float2(f2tff(acc[c][a][0] * inv0),
                                    f2tff(acc[c][a][1] * inv0));
            float2 w1 = make_float2(f2tff(acc[c][a][2] * inv1),
                                    f2tff(acc[c][a][3] * inv1));
            *(float2*)(ag + gr0 + key) = w0;
            *(float2*)(ag + gr1 + key) = w1;
            const int u = pub + a * 2 + (t >> 1);
            const uint32_t off = (t & 1) * 8;
            *(float2*)(smem + pkc * 4096 + lr0 * 128 + ((u ^ (lr0 & 7)) << 4) + off) = w0;
            *(float2*)(smem + pkc * 4096 + lr1 * 128 + ((u ^ (lr1 & 7)) << 4) + off) = w1;
        }
        if (c < 7) { loadV(c + 1, (c + 1) & 1); CP_COMMIT(); CP_WAIT(1); }
        else       { CP_WAIT(0); }
        __syncthreads();

        const uint32_t vst = VS + (c & 1) * 32768;
        #pragma unroll
        for (int ks = 0; ks < 16; ks += 2) {
            const int u0 = (ks & 3) * 2;   // 0 or 4
            unsigned bf[4];
            LDSM4(bf[0], bf[1], bf[2], bf[3],
                  vst + (ks >> 2) * 8192 + pbrow * 128 + (((u0 + sub) ^ (pbrow & 7)) << 4));
            #pragma unroll
            for (int kk = 0; kk < 2; kk++) {
                const int kss = ks + kk;
                const uint32_t au = ((kss & 3) * 2 + asel) ^ (parow & 7);
                unsigned af[4];
                LDSM4(af[0], af[1], af[2], af[3],
                      PS + (kss >> 2) * 4096 + parow * 128 + (au << 4));
                mma_tf32(acc2, af, &bf[kk * 2]);
            }
        }
        __syncthreads();
    }

    // ---- ctx epilogue: rounded, remapped [B,S,H*Dv] ----
    {
        const int b = bz >> 4, h = bz & 15;
        const int crow0 = row0 + wM * 16 + g;
        const int crow1 = crow0 + 8;
        const int ccol = wN * 8 + 2 * t;
        float2 c0 = make_float2(f2tff(acc2[0]), f2tff(acc2[1]));
        float2 c1 = make_float2(f2tff(acc2[2]), f2tff(acc2[3]));
        *(float2*)(ctx + ((size_t)b * SEQ + crow0) * DMODEL + h * DKV + ccol) = c0;
        *(float2*)(ctx + ((size_t)b * SEQ + crow1) * DMODEL + h * DKV + ccol) = c1;
    }
}

// ---------------- layernorm over last dim 1024 ----------------
template<bool DUAL>
__global__ void __launch_bounds__(256) layernorm_rows(
    const float* __restrict__ in, const float* __restrict__ g,
    const float* __restrict__ bta, float* __restrict__ out,
    float* __restrict__ out_r)
{
    __shared__ float s1w[8], s2w[8];
    const size_t row = blockIdx.x;
    const float* p = in + row * DMODEL;
    const int tid = threadIdx.x, lane = tid & 31, wid = tid >> 5;
    float4 v = *(const float4*)(p + tid*4);
    float s1 = v.x + v.y + v.z + v.w;
    float s2 = v.x*v.x + v.y*v.y + v.z*v.z + v.w*v.w;
    #pragma unroll
    for (int o = 16; o; o >>= 1) {
        s1 += __shfl_xor_sync(~0u, s1, o);
        s2 += __shfl_xor_sync(~0u, s2, o);
    }
    if (lane == 0) { s1w[wid] = s1; s2w[wid] = s2; }
    __syncthreads();
    s1 = s1w[0]; s2 = s2w[0];
    #pragma unroll
    for (int i = 1; i < 8; i++) { s1 += s1w[i]; s2 += s2w[i]; }
    const float mu  = s1 * (1.f/DMODEL);
    const float var = s2 * (1.f/DMODEL) - mu*mu;
    const float rs  = rsqrtf(var + 1e-5f);
    float4 gv = *(const float4*)(g + tid*4);
    float4 bv = *(const float4*)(bta + tid*4);
    float4 o;
    o.x = (v.x - mu)*rs*gv.x + bv.x;
    o.y = (v.y - mu)*rs*gv.y + bv.y;
    o.z = (v.z - mu)*rs*gv.z + bv.z;
    o.w = (v.w - mu)*rs*gv.w + bv.w;
    *(float4*)(out + row*DMODEL + tid*4) = o;
    if (DUAL) {
        float4 r;
        r.x = f2tff(o.x); r.y = f2tff(o.y); r.z = f2tff(o.z); r.w = f2tff(o.w);
        *(float4*)(out_r + row*DMODEL + tid*4) = r;
    }
}

// ---------------- launch ----------------
extern "C" void kernel_launch(void* const* d_in, const int* in_sizes, int n_in,
                              void* d_out, int out_size)
{
    const float* x    = (const float*)d_in[0];
    const unsigned char* mask = (const unsigned char*)d_in[1];
    const float* Wq = (const float*)d_in[2];  const float* bq = (const float*)d_in[3];
    const float* Wk = (const float*)d_in[4];  const float* bk = (const float*)d_in[5];
    const float* Wv = (const float*)d_in[6];  const float* bv = (const float*)d_in[7];
    const float* Wo = (const float*)d_in[8];  const float* bo = (const float*)d_in[9];
    const float* ln1g = (const float*)d_in[10]; const float* ln1b = (const float*)d_in[11];
    const float* W1 = (const float*)d_in[12]; const float* b1 = (const float*)d_in[13];
    const float* W2 = (const float*)d_in[14]; const float* b2 = (const float*)d_in[15];
    const float* ln2g = (const float*)d_in[16]; const float* ln2b = (const float*)d_in[17];

    float* out = (float*)d_out;
    float* ffn_out = out;                                    // [B,S,D]
    float* attn    = out + (size_t)MROWS * DMODEL;           // [B,H,S,S]

    float *qp, *kp, *vTp, *ctxp, *tmpp, *aop, *aorp, *xrp, *hp;
    float *wqT, *wkT, *wvT, *woT, *w1T, *w2T;
    cudaGetSymbolAddress((void**)&qp,   g_q);
    cudaGetSymbolAddress((void**)&kp,   g_k);
    cudaGetSymbolAddress((void**)&vTp,  g_vT);
    cudaGetSymbolAddress((void**)&ctxp, g_ctx);
    cudaGetSymbolAddress((void**)&tmpp, g_tmp);
    cudaGetSymbolAddress((void**)&aop,  g_ao);
    cudaGetSymbolAddress((void**)&aorp, g_aor);
    cudaGetSymbolAddress((void**)&xrp,  g_xr);
    cudaGetSymbolAddress((void**)&hp,   g_h);
    cudaGetSymbolAddress((void**)&wqT,  g_wqT);
    cudaGetSymbolAddress((void**)&wkT,  g_wkT);
    cudaGetSymbolAddress((void**)&wvT,  g_wvT);
    cudaGetSymbolAddress((void**)&woT,  g_woT);
    cudaGetSymbolAddress((void**)&w1T,  g_w1T);
    cudaGetSymbolAddress((void**)&w2T,  g_w2T);

    const int SM128 = 3 * (128*128 + 128*128);   // 98,304 B
    const int SMFA  = 81920 + 32*9*4;            // 83,072 B
    cudaFuncSetAttribute(tc_mma<128,1>, cudaFuncAttributeMaxDynamicSharedMemorySize, SM128);
    cudaFuncSetAttribute(tc_mma<128,2>, cudaFuncAttributeMaxDynamicSharedMemorySize, SM128);
    cudaFuncSetAttribute(tc_mma<128,3>, cudaFuncAttributeMaxDynamicSharedMemorySize, SM128);
    cudaFuncSetAttribute(tc_mma<128,6>, cudaFuncAttributeMaxDynamicSharedMemorySize, SM128);
    cudaFuncSetAttribute(fused_attn, cudaFuncAttributeMaxDynamicSharedMemorySize, SMFA);

    // ---- prep: round x; transpose+round all weights ----
    round_tf<<<(MROWS*DMODEL/4 + 255)/256, 256>>>(x, xrp, MROWS*DMODEL/4);
    dim3 tb(32, 8);
    transpose_round<<<dim3(32, 32),  tb>>>(Wq, wqT, DMODEL, DMODEL);
    transpose_round<<<dim3(32, 32),  tb>>>(Wk, wkT, DMODEL, DMODEL);
    transpose_round<<<dim3(32, 32),  tb>>>(Wv, wvT, DMODEL, DMODEL);
    transpose_round<<<dim3(32, 32),  tb>>>(Wo, woT, DMODEL, DMODEL);
    transpose_round<<<dim3(128, 32), tb>>>(W1, w1T, DMODEL, DFF);
    transpose_round<<<dim3(32, 128), tb>>>(W2, w2T, DFF, DMODEL);

    // ---- Q + K projections in one launch (z selects weight/bias/output) ----
    tc_mma<128,1><<<dim3(8,64,2),256,SM128>>>(xrp, wqT, bq, nullptr, qp,
                                              wkT, bk, kp, DMODEL, DMODEL);
    // ---- V projection, transposed orientation: vT = WvT(A) x xr(B) ----
    tc_mma<128,6><<<dim3(64,8,1),256,SM128>>>(wvT, xrp, bv, nullptr, vTp,
                                              nullptr, nullptr, nullptr,
                                              DMODEL, MROWS);

    // ---- fused attention: scores+mask+softmax -> attn (rounded) + ctx ----
    fused_attn<<<dim3(32, BH), 512, SMFA>>>(qp, kp, vTp, mask, attn, ctxp);

    // ---- out proj + residual, LN1 (dual fp32 + rounded) ----
    tc_mma<128,2><<<dim3(8,64,1),256,SM128>>>(ctxp, woT, bo, x, tmpp,
                                              nullptr, nullptr, nullptr,
                                              DMODEL, DMODEL);
    layernorm_rows<true><<<MROWS, 256>>>(tmpp, ln1g, ln1b, aop, aorp);

    // ---- FFN ----
    tc_mma<128,3><<<dim3(32,64,1),256,SM128>>>(aorp, w1T, b1, nullptr, hp,
                                               nullptr, nullptr, nullptr,
                                               DMODEL, DFF);
    tc_mma<128,2><<<dim3(8,64,1),256,SM128>>>(hp, w2T, b2, aop, tmpp,
                                              nullptr, nullptr, nullptr,
                                              DFF, DMODEL);
    layernorm_rows<false><<<MROWS, 256>>>(tmpp, ln2g, ln2b, ffn_out, nullptr);
}

// round 16
// speedup vs baseline: 1.0520x; 1.0520x over previous
#include <cuda_runtime.h>
#include <cstdint>
#include <math.h>

#define DMODEL 1024
#define DFF    4096
#define NHEADS 16
#define DKV    64
#define BATCH  8
#define SEQ    1024
#define MROWS  (BATCH*SEQ)    // 8192
#define BH     (BATCH*NHEADS) // 128

// ---------------- scratch (no allocations allowed) ----------------
__device__ __align__(256) float g_q[BH*SEQ*DKV];        // [B,H,S,Dk] rounded
__device__ __align__(256) float g_k[BH*SEQ*DKV];        // [B,H,S,Dk] rounded
__device__ __align__(256) float g_vT[BH*DKV*SEQ];       // [B,H,Dv,S] rounded
__device__ __align__(256) float g_ctx[MROWS*DMODEL];    // rounded
__device__ __align__(256) float g_tmp[MROWS*DMODEL];    // pre-LN fp32
__device__ __align__(256) float g_ao[MROWS*DMODEL];     // LN1 fp32 (residual)
__device__ __align__(256) float g_aor[MROWS*DMODEL];    // LN1 rounded
__device__ __align__(256) float g_xr[MROWS*DMODEL];     // x rounded
__device__ __align__(256) float g_h[(size_t)MROWS*DFF]; // hidden rounded
__device__ __align__(256) float g_wqT[DMODEL*DMODEL];   // W^T rounded (K-major)
__device__ __align__(256) float g_wkT[DMODEL*DMODEL];
__device__ __align__(256) float g_wvT[DMODEL*DMODEL];
__device__ __align__(256) float g_woT[DMODEL*DMODEL];
__device__ __align__(256) float g_w1T[(size_t)DMODEL*DFF];
__device__ __align__(256) float g_w2T[(size_t)DFF*DMODEL];

// ---------------- helpers ----------------
__device__ __forceinline__ unsigned f2tf(float x) {
    unsigned u;
    asm("cvt.rna.tf32.f32 %0, %1;" : "=r"(u) : "f"(x));
    return u;
}
__device__ __forceinline__ float f2tff(float x) { return __uint_as_float(f2tf(x)); }

__device__ __forceinline__ unsigned sptr(const void* p) {
    return (unsigned)__cvta_generic_to_shared(p);
}
#define CP_ASYNC16(dst, src) \
    asm volatile("cp.async.cg.shared.global [%0], [%1], 16;" :: "r"(dst), "l"(src))
#define CP_COMMIT() asm volatile("cp.async.commit_group;")
#define CP_WAIT(n)  asm volatile("cp.async.wait_group %0;" :: "n"(n))

#define LDSM4(r0, r1, r2, r3, a) \
    asm volatile("ldmatrix.sync.aligned.m8n8.x4.shared.b16 {%0,%1,%2,%3}, [%4];" \
                 : "=r"(r0), "=r"(r1), "=r"(r2), "=r"(r3) : "r"(a))

__device__ __forceinline__ void mma_tf32(float* c, const unsigned* a, const unsigned* b) {
    asm volatile(
        "mma.sync.aligned.m16n8k8.row.col.f32.tf32.tf32.f32 "
        "{%0,%1,%2,%3},{%4,%5,%6,%7},{%8,%9},{%0,%1,%2,%3};"
        : "+f"(c[0]), "+f"(c[1]), "+f"(c[2]), "+f"(c[3])
        : "r"(a[0]), "r"(a[1]), "r"(a[2]), "r"(a[3]), "r"(b[0]), "r"(b[1]));
}

// ---------------- prep kernels ----------------
__global__ void round_tf(const float* __restrict__ in, float* __restrict__ out, int n4)
{
    int i = blockIdx.x * blockDim.x + threadIdx.x;
    if (i < n4) {
        float4 v = ((const float4*)in)[i];
        v.x = f2tff(v.x); v.y = f2tff(v.y); v.z = f2tff(v.z); v.w = f2tff(v.w);
        ((float4*)out)[i] = v;
    }
}

// in [R][C] -> out [C][R], tf32-rounded
__global__ void transpose_round(const float* __restrict__ in, float* __restrict__ out,
                                int R, int C)
{
    __shared__ float t[32][33];
    const int c0 = blockIdx.x * 32, r0 = blockIdx.y * 32;
    const int tx = threadIdx.x, ty = threadIdx.y;   // 32 x 8
    #pragma unroll
    for (int i = 0; i < 32; i += 8)
        t[ty + i][tx] = in[(size_t)(r0 + ty + i) * C + c0 + tx];
    __syncthreads();
    #pragma unroll
    for (int i = 0; i < 32; i += 8)
        out[(size_t)(c0 + ty + i) * R + r0 + tx] = f2tff(t[tx][ty + i]);
}

// =====================================================================
// mma.sync tf32 GEMM, ldmatrix fragments, cp.async staging, BK=32.
// D[m][n] = sum_k A[m][k] * B[n][k], both operands K-major, pre-rounded.
// Block tile 128 x NTILE, 8 warps (2M x 4N), warp tile 64 x (NTILE/4).
// MODE: 1 q/k-remap(+bias,round; z selects {B,bias,C} vs {B2,bias2,C2})
//       2 +bias+resid  3 relu(+bias,round)
//       5 ctx-remap(round; z = batch via strides)
//       6 vT transposed remap(+bias-by-row,round)
// =====================================================================
template<int NTILE, int MODE>
__global__ void __launch_bounds__(256, 2) tc_mma(
    const float* __restrict__ A, const float* __restrict__ B,
    const float* __restrict__ bias, const float* __restrict__ resid,
    float* __restrict__ C,
    const float* __restrict__ B2, const float* __restrict__ bias2,
    float* __restrict__ C2,
    int K, int N, long long sA, long long sB)
{
    constexpr int S = 3;
    constexpr int ABYTES = 128 * 128;          // 128 rows x 128B
    constexpr int BBYTES = NTILE * 128;
    constexpr int STAGE  = ABYTES + BBYTES;
    constexpr int NP = NTILE / 64;             // ldmatrix x4 B pairs per warp
    constexpr int NT = NTILE / 32;             // 8-wide n atoms per warp

    extern __shared__ __align__(128) char smem[];
    const uint32_t ST0 = sptr(smem);

    const int tid = threadIdx.x;
    const int lane = tid & 31, wid = tid >> 5;
    const int warpM = wid >> 2, warpN = wid & 3;
    const int g = lane >> 2, t = lane & 3;
    const int sub = lane >> 3, lr = lane & 7;
    const int asel = sub >> 1, bsel = sub & 1;

    const int bm = blockIdx.y, bn = blockIdx.x, bz = blockIdx.z;
    if (MODE == 1) {
        if (bz == 1) { B = B2; bias = bias2; C = C2; }
    } else if (MODE == 5) {
        A += (long long)bz * sA;
        B += (long long)bz * sB;
    }

    const float* Aload = A + (size_t)bm * 128 * K;
    const float* Bload = B + (size_t)bn * NTILE * K;

    const int arow = tid >> 1, ahalf = tid & 1;
    const float* Ag = Aload + (size_t)arow * K + ahalf * 16;
    const int brow = (NTILE == 128) ? (tid >> 1) : (tid >> 2);
    const int bu0  = (NTILE == 128) ? (ahalf * 4) : ((tid & 3) * 2);
    const float* Bg = Bload + (size_t)brow * K + bu0 * 4;

    auto load_chunk = [&](int ch) {
        const uint32_t stA = ST0 + (ch % S) * STAGE;
        const uint32_t stB = stA + ABYTES;
        const float* ap = Ag + ch * 32;
        const uint32_t abase = stA + arow * 128;
        #pragma unroll
        for (int i = 0; i < 4; i++) {
            const int u = ahalf * 4 + i;
            CP_ASYNC16(abase + ((u ^ (arow & 7)) << 4), ap + i * 4);
        }
        const float* bp = Bg + ch * 32;
        const uint32_t bbase = stB + brow * 128;
        #pragma unroll
        for (int i = 0; i < (NTILE == 128 ? 4 : 2); i++) {
            const int u = bu0 + i;
            CP_ASYNC16(bbase + ((u ^ (brow & 7)) << 4), bp + i * 4);
        }
    };

    uint32_t arow_b[4], brow_b[NP];
    #pragma unroll
    for (int mt = 0; mt < 4; mt++)
        arow_b[mt] = (warpM * 64 + mt * 16 + (sub & 1) * 8 + lr) * 128;
    #pragma unroll
    for (int np = 0; np < NP; np++)
        brow_b[np] = (warpN * (NTILE / 4) + np * 16 + asel * 8 + lr) * 128;

    float acc[4][NT][4];
    #pragma unroll
    for (int i = 0; i < 4; i++)
        #pragma unroll
        for (int j = 0; j < NT; j++)
            #pragma unroll
            for (int r = 0; r < 4; r++) acc[i][j][r] = 0.f;

    const int nch = K >> 5;

    #pragma unroll
    for (int c = 0; c < S - 1; c++) {
        if (c < nch) load_chunk(c);
        CP_COMMIT();
    }

    for (int ch = 0; ch < nch; ch++) {
        CP_WAIT(S - 2);
        __syncthreads();
        if (ch + S - 1 < nch) load_chunk(ch + S - 1);
        CP_COMMIT();

        const uint32_t Ast = ST0 + (ch % S) * STAGE;
        const uint32_t Bst = Ast + ABYTES;
        #pragma unroll
        for (int ks = 0; ks < 4; ks++) {
            const uint32_t aoff = (uint32_t)((((ks << 1) + asel) ^ lr) << 4);
            const uint32_t boff = (uint32_t)((((ks << 1) + bsel) ^ lr) << 4);
            unsigned af[4][4];
            #pragma unroll
            for (int mt = 0; mt < 4; mt++)
                LDSM4(af[mt][0], af[mt][1], af[mt][2], af[mt][3],
                      Ast + arow_b[mt] + aoff);
            unsigned bf[NP][4];
            #pragma unroll
            for (int np = 0; np < NP; np++)
                LDSM4(bf[np][0], bf[np][1], bf[np][2], bf[np][3],
                      Bst + brow_b[np] + boff);
            #pragma unroll
            for (int mt = 0; mt < 4; mt++)
                #pragma unroll
                for (int np = 0; np < NP; np++) {
                    mma_tf32(acc[mt][np * 2],     af[mt], &bf[np][0]);
                    mma_tf32(acc[mt][np * 2 + 1], af[mt], &bf[np][2]);
                }
        }
    }

    // ---- epilogue ----
    #pragma unroll
    for (int mt = 0; mt < 4; mt++) {
        const int r0 = bm * 128 + warpM * 64 + mt * 16 + g;
        const int r1 = r0 + 8;
        #pragma unroll
        for (int nt = 0; nt < NT; nt++) {
            const int c = bn * NTILE + warpN * (NTILE / 4) + nt * 8 + 2 * t;
            float2 lo = make_float2(acc[mt][nt][0], acc[mt][nt][1]);  // row r0
            float2 hi = make_float2(acc[mt][nt][2], acc[mt][nt][3]);  // row r1

            if (MODE == 1 || MODE == 2 || MODE == 3) {
                const float2 bv = *(const float2*)(bias + c);
                lo.x += bv.x; lo.y += bv.y; hi.x += bv.x; hi.y += bv.y;
            }
            if (MODE == 6) {
                const float b0 = bias[r0], b1 = bias[r1];
                lo.x = f2tff(lo.x + b0); lo.y = f2tff(lo.y + b0);
                hi.x = f2tff(hi.x + b1); hi.y = f2tff(hi.y + b1);
            }
            if (MODE == 2) {
                const float2 q0 = *(const float2*)(resid + (size_t)r0 * N + c);
                const float2 q1 = *(const float2*)(resid + (size_t)r1 * N + c);
                lo.x += q0.x; lo.y += q0.y; hi.x += q1.x; hi.y += q1.y;
            }
            if (MODE == 3) {
                lo.x = f2tff(fmaxf(lo.x, 0.f)); lo.y = f2tff(fmaxf(lo.y, 0.f));
                hi.x = f2tff(fmaxf(hi.x, 0.f)); hi.y = f2tff(fmaxf(hi.y, 0.f));
            }

            if (MODE == 1) {
                lo.x = f2tff(lo.x); lo.y = f2tff(lo.y);
                hi.x = f2tff(hi.x); hi.y = f2tff(hi.y);
                const int h = c >> 6, d = c & 63;
                const int bb0 = r0 >> 10, s0 = r0 & 1023;
                const int bb1 = r1 >> 10, s1 = r1 & 1023;
                *(float2*)(C + (((size_t)(bb0*NHEADS + h))*SEQ + s0)*DKV + d) = lo;
                *(float2*)(C + (((size_t)(bb1*NHEADS + h))*SEQ + s1)*DKV + d) = hi;
            } else if (MODE == 5) {
                lo.x = f2tff(lo.x); lo.y = f2tff(lo.y);
                hi.x = f2tff(hi.x); hi.y = f2tff(hi.y);
                const int b = bz >> 4, h = bz & 15;
                *(float2*)(C + ((size_t)b*SEQ + r0)*DMODEL + h*DKV + c) = lo;
                *(float2*)(C + ((size_t)b*SEQ + r1)*DMODEL + h*DKV + c) = hi;
            } else if (MODE == 6) {
                const int b = c >> 10, s = c & 1023;
                const int h0 = r0 >> 6, d0 = r0 & 63;
                const int h1 = r1 >> 6, d1 = r1 & 63;
                *(float2*)(C + (((size_t)(b*NHEADS + h0))*DKV + d0)*SEQ + s) = lo;
                *(float2*)(C + (((size_t)(b*NHEADS + h1))*DKV + d1)*SEQ + s) = hi;
            } else {
                *(float2*)(C + (size_t)r0 * N + c) = lo;
                *(float2*)(C + (size_t)r1 * N + c) = hi;
            }
        }
    }
}

// =====================================================================
// Fused scores + mask + softmax (16-row blocks, 2 CTAs/SM).
// Block: 16 q-rows x all 1024 keys, 256 thr = 8 warps (1M x 8N).
// Warp wN owns keys wN*16..+16 of each 128-key chunk (same key partition
// and accumulation order as the 32-row version -> bit-identical results).
// =====================================================================
__global__ void __launch_bounds__(256, 2) fused_scores_softmax16(
    const float* __restrict__ q, const float* __restrict__ k,
    const unsigned char* __restrict__ mask, float* __restrict__ attn)
{
    extern __shared__ __align__(128) char smem[];
    const uint32_t QS = sptr(smem);            // Q: 2kc x 16r x 128B = 4KB
    const uint32_t KS = QS + 4096;             // K: 2 stages x 32KB
    float* stats = (float*)(smem + 4096 + 65536);   // [16][9]

    const int tid = threadIdx.x;
    const int lane = tid & 31, wN = tid >> 5;   // 8 warps, all same M group
    const int g = lane >> 2, t = lane & 3;
    const int sub = lane >> 3, lr = lane & 7;
    const int asel = sub >> 1, bsel = sub & 1;

    const int bz = blockIdx.y;
    const int row0 = blockIdx.x * 16;
    const float* qg = q + (size_t)bz * SEQ * DKV + (size_t)row0 * DKV;
    const float* kg = k + (size_t)bz * SEQ * DKV;
    float* ag = attn + (size_t)bz * SEQ * SEQ;
    const unsigned char* mb = mask + (size_t)(bz >> 4) * SEQ * SEQ;

    // load Q tile (4KB): thread -> one 16B unit
    {
        const int u = tid & 7, row = (tid >> 3) & 15, kc = tid >> 7;
        CP_ASYNC16(QS + kc * 2048 + row * 128 + ((u ^ (row & 7)) << 4),
                   qg + (size_t)row * DKV + kc * 32 + u * 4);
    }
    auto loadK = [&](int c, int st) {
        const uint32_t stB = KS + st * 32768;
        const float* kb = kg + (size_t)c * 128 * DKV;
        #pragma unroll
        for (int i = 0; i < 8; i++) {
            const int idx = tid + i * 256;
            const int u = idx & 7, krow = (idx >> 3) & 127, kc = idx >> 10;
            CP_ASYNC16(stB + kc * 16384 + krow * 128 + ((u ^ (krow & 7)) << 4),
                       kb + (size_t)krow * DKV + kc * 32 + u * 4);
        }
    };

    float acc[8][2][4];
    #pragma unroll
    for (int c = 0; c < 8; c++)
        #pragma unroll
        for (int a = 0; a < 2; a++)
            #pragma unroll
            for (int r = 0; r < 4; r++) acc[c][a][r] = 0.f;

    loadK(0, 0); CP_COMMIT();

    const uint32_t arow128 = ((sub & 1) * 8 + lr) * 128;        // rows within 16
    const uint32_t brow128 = (wN * 16 + asel * 8 + lr) * 128;

    for (int c = 0; c < 8; c++) {
        if (c < 7) { loadK(c + 1, (c + 1) & 1); CP_COMMIT(); CP_WAIT(1); }
        else       { CP_WAIT(0); }
        __syncthreads();
        const uint32_t stB = KS + (c & 1) * 32768;
        #pragma unroll
        for (int ks = 0; ks < 8; ks++) {
            const int kc = ks >> 2;
            const uint32_t aoff = (uint32_t)(((((ks & 3) << 1) + asel) ^ lr) << 4);
            const uint32_t boff = (uint32_t)(((((ks & 3) << 1) + bsel) ^ lr) << 4);
            unsigned af[4], bf[4];
            LDSM4(af[0], af[1], af[2], af[3], QS + kc * 2048 + arow128 + aoff);
            LDSM4(bf[0], bf[1], bf[2], bf[3], stB + kc * 16384 + brow128 + boff);
            mma_tf32(acc[c][0], af, &bf[0]);
            mma_tf32(acc[c][1], af, &bf[2]);
        }
        __syncthreads();
    }

    // ---- softmax ----
    const int lr0 = g, lr1 = g + 8;            // local rows within 16
    const size_t gr0 = (size_t)(row0 + lr0) * SEQ;
    const size_t gr1 = (size_t)(row0 + lr1) * SEQ;

    float m0 = -1e30f, m1 = -1e30f;
    #pragma unroll
    for (int c = 0; c < 8; c++)
        #pragma unroll
        for (int a = 0; a < 2; a++) {
            const int key = c * 128 + wN * 16 + a * 8 + 2 * t;
            float v0 = acc[c][a][0] * 0.125f, v1 = acc[c][a][1] * 0.125f;
            float v2 = acc[c][a][2] * 0.125f, v3 = acc[c][a][3] * 0.125f;
            if (mb[gr0 + key])     v0 = -1e9f;
            if (mb[gr0 + key + 1]) v1 = -1e9f;
            if (mb[gr1 + key])     v2 = -1e9f;
            if (mb[gr1 + key + 1]) v3 = -1e9f;
            acc[c][a][0] = v0; acc[c][a][1] = v1;
            acc[c][a][2] = v2; acc[c][a][3] = v3;
            m0 = fmaxf(m0, fmaxf(v0, v1));
            m1 = fmaxf(m1, fmaxf(v2, v3));
        }
    m0 = fmaxf(m0, __shfl_xor_sync(~0u, m0, 1));
    m0 = fmaxf(m0, __shfl_xor_sync(~0u, m0, 2));
    m1 = fmaxf(m1, __shfl_xor_sync(~0u, m1, 1));
    m1 = fmaxf(m1, __shfl_xor_sync(~0u, m1, 2));
    if (t == 0) { stats[lr0 * 9 + wN] = m0; stats[lr1 * 9 + wN] = m1; }
    __syncthreads();
    float M0 = stats[lr0 * 9], M1 = stats[lr1 * 9];
    #pragma unroll
    for (int i = 1; i < 8; i++) {
        M0 = fmaxf(M0, stats[lr0 * 9 + i]);
        M1 = fmaxf(M1, stats[lr1 * 9 + i]);
    }
    __syncthreads();

    float s0 = 0.f, s1 = 0.f;
    #pragma unroll
    for (int c = 0; c < 8; c++)
        #pragma unroll
        for (int a = 0; a < 2; a++) {
            float e0 = __expf(acc[c][a][0] - M0), e1 = __expf(acc[c][a][1] - M0);
            float e2 = __expf(acc[c][a][2] - M1), e3 = __expf(acc[c][a][3] - M1);
            acc[c][a][0] = e0; acc[c][a][1] = e1;
            acc[c][a][2] = e2; acc[c][a][3] = e3;
            s0 += e0 + e1; s1 += e2 + e3;
        }
    s0 += __shfl_xor_sync(~0u, s0, 1); s0 += __shfl_xor_sync(~0u, s0, 2);
    s1 += __shfl_xor_sync(~0u, s1, 1); s1 += __shfl_xor_sync(~0u, s1, 2);
    if (t == 0) { stats[lr0 * 9 + wN] = s0; stats[lr1 * 9 + wN] = s1; }
    __syncthreads();
    float S0 = 0.f, S1 = 0.f;
    #pragma unroll
    for (int i = 0; i < 8; i++) { S0 += stats[lr0 * 9 + i]; S1 += stats[lr1 * 9 + i]; }
    const float inv0 = 1.f / S0, inv1 = 1.f / S1;

    #pragma unroll
    for (int c = 0; c < 8; c++)
        #pragma unroll
        for (int a = 0; a < 2; a++) {
            const int key = c * 128 + wN * 16 + a * 8 + 2 * t;
            float2 w0 = make_float2(f2tff(acc[c][a][0] * inv0),
                                    f2tff(acc[c][a][1] * inv0));
            float2 w1 = make_float2(f2tff(acc[c][a][2] * inv1),
                                    f2tff(acc[c][a][3] * inv1));
            *(float2*)(ag + gr0 + key) = w0;
            *(float2*)(ag + gr1 + key) = w1;
        }
}

// ---------------- layernorm over last dim 1024 ----------------
template<bool DUAL>
__global__ void __launch_bounds__(256) layernorm_rows(
    const float* __restrict__ in, const float* __restrict__ g,
    const float* __restrict__ bta, float* __restrict__ out,
    float* __restrict__ out_r)
{
    __shared__ float s1w[8], s2w[8];
    const size_t row = blockIdx.x;
    const float* p = in + row * DMODEL;
    const int tid = threadIdx.x, lane = tid & 31, wid = tid >> 5;
    float4 v = *(const float4*)(p + tid*4);
    float s1 = v.x + v.y + v.z + v.w;
    float s2 = v.x*v.x + v.y*v.y + v.z*v.z + v.w*v.w;
    #pragma unroll
    for (int o = 16; o; o >>= 1) {
        s1 += __shfl_xor_sync(~0u, s1, o);
        s2 += __shfl_xor_sync(~0u, s2, o);
    }
    if (lane == 0) { s1w[wid] = s1; s2w[wid] = s2; }
    __syncthreads();
    s1 = s1w[0]; s2 = s2w[0];
    #pragma unroll
    for (int i = 1; i < 8; i++) { s1 += s1w[i]; s2 += s2w[i]; }
    const float mu  = s1 * (1.f/DMODEL);
    const float var = s2 * (1.f/DMODEL) - mu*mu;
    const float rs  = rsqrtf(var + 1e-5f);
    float4 gv = *(const float4*)(g + tid*4);
    float4 bv = *(const float4*)(bta + tid*4);
    float4 o;
    o.x = (v.x - mu)*rs*gv.x + bv.x;
    o.y = (v.y - mu)*rs*gv.y + bv.y;
    o.z = (v.z - mu)*rs*gv.z + bv.z;
    o.w = (v.w - mu)*rs*gv.w + bv.w;
    *(float4*)(out + row*DMODEL + tid*4) = o;
    if (DUAL) {
        float4 r;
        r.x = f2tff(o.x); r.y = f2tff(o.y); r.z = f2tff(o.z); r.w = f2tff(o.w);
        *(float4*)(out_r + row*DMODEL + tid*4) = r;
    }
}

// ---------------- launch ----------------
extern "C" void kernel_launch(void* const* d_in, const int* in_sizes, int n_in,
                              void* d_out, int out_size)
{
    const float* x    = (const float*)d_in[0];
    const unsigned char* mask = (const unsigned char*)d_in[1];
    const float* Wq = (const float*)d_in[2];  const float* bq = (const float*)d_in[3];
    const float* Wk = (const float*)d_in[4];  const float* bk = (const float*)d_in[5];
    const float* Wv = (const float*)d_in[6];  const float* bv = (const float*)d_in[7];
    const float* Wo = (const float*)d_in[8];  const float* bo = (const float*)d_in[9];
    const float* ln1g = (const float*)d_in[10]; const float* ln1b = (const float*)d_in[11];
    const float* W1 = (const float*)d_in[12]; const float* b1 = (const float*)d_in[13];
    const float* W2 = (const float*)d_in[14]; const float* b2 = (const float*)d_in[15];
    const float* ln2g = (const float*)d_in[16]; const float* ln2b = (const float*)d_in[17];

    float* out = (float*)d_out;
    float* ffn_out = out;                                    // [B,S,D]
    float* attn    = out + (size_t)MROWS * DMODEL;           // [B,H,S,S]

    float *qp, *kp, *vTp, *ctxp, *tmpp, *aop, *aorp, *xrp, *hp;
    float *wqT, *wkT, *wvT, *woT, *w1T, *w2T;
    cudaGetSymbolAddress((void**)&qp,   g_q);
    cudaGetSymbolAddress((void**)&kp,   g_k);
    cudaGetSymbolAddress((void**)&vTp,  g_vT);
    cudaGetSymbolAddress((void**)&ctxp, g_ctx);
    cudaGetSymbolAddress((void**)&tmpp, g_tmp);
    cudaGetSymbolAddress((void**)&aop,  g_ao);
    cudaGetSymbolAddress((void**)&aorp, g_aor);
    cudaGetSymbolAddress((void**)&xrp,  g_xr);
    cudaGetSymbolAddress((void**)&hp,   g_h);
    cudaGetSymbolAddress((void**)&wqT,  g_wqT);
    cudaGetSymbolAddress((void**)&wkT,  g_wkT);
    cudaGetSymbolAddress((void**)&wvT,  g_wvT);
    cudaGetSymbolAddress((void**)&woT,  g_woT);
    cudaGetSymbolAddress((void**)&w1T,  g_w1T);
    cudaGetSymbolAddress((void**)&w2T,  g_w2T);

    const int SM128 = 3 * (128*128 + 128*128);   // 98,304 B
    const int SM64  = 3 * (128*128 +  64*128);   // 73,728 B
    const int SMF16 = 4096 + 65536 + 16*9*4;     // 70,208 B
    cudaFuncSetAttribute(tc_mma<128,1>, cudaFuncAttributeMaxDynamicSharedMemorySize, SM128);
    cudaFuncSetAttribute(tc_mma<128,2>, cudaFuncAttributeMaxDynamicSharedMemorySize, SM128);
    cudaFuncSetAttribute(tc_mma<128,3>, cudaFuncAttributeMaxDynamicSharedMemorySize, SM128);
    cudaFuncSetAttribute(tc_mma<128,6>, cudaFuncAttributeMaxDynamicSharedMemorySize, SM128);
    cudaFuncSetAttribute(tc_mma<64,5>,  cudaFuncAttributeMaxDynamicSharedMemorySize, SM64);
    cudaFuncSetAttribute(fused_scores_softmax16, cudaFuncAttributeMaxDynamicSharedMemorySize, SMF16);

    // ---- prep: round x; transpose+round all weights ----
    round_tf<<<(MROWS*DMODEL/4 + 255)/256, 256>>>(x, xrp, MROWS*DMODEL/4);
    dim3 tb(32, 8);
    transpose_round<<<dim3(32, 32),  tb>>>(Wq, wqT, DMODEL, DMODEL);
    transpose_round<<<dim3(32, 32),  tb>>>(Wk, wkT, DMODEL, DMODEL);
    transpose_round<<<dim3(32, 32),  tb>>>(Wv, wvT, DMODEL, DMODEL);
    transpose_round<<<dim3(32, 32),  tb>>>(Wo, woT, DMODEL, DMODEL);
    transpose_round<<<dim3(128, 32), tb>>>(W1, w1T, DMODEL, DFF);
    transpose_round<<<dim3(32, 128), tb>>>(W2, w2T, DFF, DMODEL);

    // ---- Q + K projections in one launch (z selects weight/bias/output) ----
    tc_mma<128,1><<<dim3(8,64,2),256,SM128>>>(xrp, wqT, bq, nullptr, qp,
                                              wkT, bk, kp, DMODEL, DMODEL, 0, 0);
    // ---- V projection, transposed orientation: vT = WvT(A) x xr(B) ----
    tc_mma<128,6><<<dim3(64,8,1),256,SM128>>>(wvT, xrp, bv, nullptr, vTp,
                                              nullptr, nullptr, nullptr,
                                              DMODEL, MROWS, 0, 0);

    // ---- fused scores + mask + softmax -> attn (rounded) ----
    fused_scores_softmax16<<<dim3(64, BH), 256, SMF16>>>(qp, kp, mask, attn);

    // ---- ctx = attn @ vT -> [B,S,H*Dv] rounded ----
    tc_mma<64,5><<<dim3(1,8,BH),256,SM64>>>(attn, vTp, nullptr, nullptr, ctxp,
                                            nullptr, nullptr, nullptr,
                                            SEQ, DKV,
                                            (long long)SEQ*SEQ, (long long)DKV*SEQ);

    // ---- out proj + residual, LN1 (dual fp32 + rounded) ----
    tc_mma<128,2><<<dim3(8,64,1),256,SM128>>>(ctxp, woT, bo, x, tmpp,
                                              nullptr, nullptr, nullptr,
                                              DMODEL, DMODEL, 0, 0);
    layernorm_rows<true><<<MROWS, 256>>>(tmpp, ln1g, ln1b, aop, aorp);

    // ---- FFN ----
    tc_mma<128,3><<<dim3(32,64,1),256,SM128>>>(aorp, w1T, b1, nullptr, hp,
                                               nullptr, nullptr, nullptr,
                                               DMODEL, DFF, 0, 0);
    tc_mma<128,2><<<dim3(8,64,1),256,SM128>>>(hp, w2T, b2, aop, tmpp,
                                              nullptr, nullptr, nullptr,
                                              DFF, DMODEL, 0, 0);
    layernorm_rows<false><<<MROWS, 256>>>(tmpp, ln2g, ln2b, ffn_out, nullptr);
}